// round 2
// baseline (speedup 1.0000x reference)
#include <cuda_runtime.h>

#define D_MODEL 1024
#define SEQ     2048
#define BATCH   2
#define NHEAD   16
#define DHEAD   64
#define HB      (NHEAD * BATCH)   // 32
#define MROWS   (BATCH * SEQ)     // 4096

// ---- device-global scratch (allocation-free per harness rules) ----
__device__ float g_q[(size_t)HB * SEQ * DHEAD];
__device__ float g_k[(size_t)HB * SEQ * DHEAD];
__device__ float g_v[(size_t)HB * SEQ * DHEAD];
__device__ float g_stage[(size_t)HB * SEQ * SEQ];       // unnormalized exp scores
__device__ float g_ctx_fb[(size_t)MROWS * D_MODEL];     // fallback ctx sink

// ---- packed fp32x2 helpers (Blackwell FFMA2; ptxas never auto-fuses) ----
__device__ __forceinline__ unsigned long long pack2(float x) {
    unsigned long long r;
    asm("mov.b64 %0, {%1, %1};" : "=l"(r) : "f"(x));
    return r;
}
__device__ __forceinline__ unsigned long long fma2(unsigned long long a,
                                                   unsigned long long b,
                                                   unsigned long long c) {
    unsigned long long d;
    asm("fma.rn.f32x2 %0, %1, %2, %3;" : "=l"(d) : "l"(a), "l"(b), "l"(c));
    return d;
}
__device__ __forceinline__ float2 unpack2(unsigned long long v) {
    float lo, hi;
    asm("mov.b64 {%0, %1}, %2;" : "=f"(lo), "=f"(hi) : "l"(v));
    return make_float2(lo, hi);
}

// ============================================================================
// Projection: out = X @ W^T + b, fused head-permute into [H*B, S, Dh].
// BM=BN=128, BK=16, 256 threads, 8x8 microtile (rows/cols split x4 + 64).
// ============================================================================
__global__ __launch_bounds__(256) void proj_kernel(
    const float* __restrict__ X, const float* __restrict__ W,
    const float* __restrict__ bias, int which)
{
    float* out = (which == 0) ? g_q : (which == 1) ? g_k : g_v;

    __shared__ float As[16 * 128];  // [kk][i]
    __shared__ float Bs[16 * 128];  // [kk][j]

    const int tid = threadIdx.x;
    const int tx = tid & 15;
    const int ty = tid >> 4;
    const int m0 = blockIdx.y * 128;
    const int n0 = blockIdx.x * 128;

    unsigned long long acc[8][4];
#pragma unroll
    for (int r = 0; r < 8; r++)
#pragma unroll
        for (int c = 0; c < 4; c++) acc[r][c] = 0ull;

    for (int k0 = 0; k0 < D_MODEL; k0 += 16) {
#pragma unroll
        for (int l = 0; l < 2; l++) {
            int id  = tid + l * 256;     // 512 float4 slots
            int row = id >> 2;           // 0..127
            int kq  = (id & 3) << 2;     // 0,4,8,12
            float4 va = *reinterpret_cast<const float4*>(
                &X[(size_t)(m0 + row) * D_MODEL + k0 + kq]);
            As[(kq + 0) * 128 + row] = va.x;
            As[(kq + 1) * 128 + row] = va.y;
            As[(kq + 2) * 128 + row] = va.z;
            As[(kq + 3) * 128 + row] = va.w;
            float4 vb = *reinterpret_cast<const float4*>(
                &W[(size_t)(n0 + row) * D_MODEL + k0 + kq]);
            Bs[(kq + 0) * 128 + row] = vb.x;
            Bs[(kq + 1) * 128 + row] = vb.y;
            Bs[(kq + 2) * 128 + row] = vb.z;
            Bs[(kq + 3) * 128 + row] = vb.w;
        }
        __syncthreads();
#pragma unroll
        for (int kk = 0; kk < 16; kk++) {
            const float* ar = &As[kk * 128];
            const float* br = &Bs[kk * 128];
            float4 af0 = *reinterpret_cast<const float4*>(ar + ty * 4);
            float4 af1 = *reinterpret_cast<const float4*>(ar + 64 + ty * 4);
            const unsigned long long* bp0 =
                reinterpret_cast<const unsigned long long*>(br + tx * 4);
            const unsigned long long* bp1 =
                reinterpret_cast<const unsigned long long*>(br + 64 + tx * 4);
            unsigned long long b0 = bp0[0], b1 = bp0[1], b2 = bp1[0], b3 = bp1[1];
            unsigned long long ap[8] = {pack2(af0.x), pack2(af0.y), pack2(af0.z), pack2(af0.w),
                                        pack2(af1.x), pack2(af1.y), pack2(af1.z), pack2(af1.w)};
#pragma unroll
            for (int r = 0; r < 8; r++) {
                acc[r][0] = fma2(ap[r], b0, acc[r][0]);
                acc[r][1] = fma2(ap[r], b1, acc[r][1]);
                acc[r][2] = fma2(ap[r], b2, acc[r][2]);
                acc[r][3] = fma2(ap[r], b3, acc[r][3]);
            }
        }
        __syncthreads();
    }

    // Epilogue: bias + head-permuted store into [h*B+b][s][d].
#pragma unroll
    for (int r = 0; r < 8; r++) {
        int gi = m0 + ty * 4 + (r & 3) + ((r >> 2) << 6);
        int b_ = gi >> 11;           // / SEQ
        int s_ = gi & (SEQ - 1);
#pragma unroll
        for (int c = 0; c < 4; c++) {
            int j = n0 + tx * 4 + ((c & 1) << 1) + ((c >> 1) << 6);
            float2 v = unpack2(acc[r][c]);
            v.x += bias[j];
            v.y += bias[j + 1];
            int h = j >> 6;
            int d = j & 63;
            *reinterpret_cast<float2*>(
                &out[((size_t)(h * BATCH + b_) * SEQ + s_) * DHEAD + d]) = v;
        }
    }
}

// ============================================================================
// Fused attention: one CTA = (head-batch n, 128 query rows), 256 threads.
// Phase 1: S = scale*(Q K^T); write exp(S - m_tile) to stage; online (m,l).
// Phase 2: p = stage * exp(m_tile - m_final)/l -> attn_out; ctx += P @ V.
// ============================================================================
// dyn smem layout (floats):
#define QS_F   0                    // phase1: [64][128]
#define KT_F   8192                 // phase1: [64][128]
#define PT_F   0                    // phase2: [128][129]
#define VS_F   16512                // phase2: [128][64]
#define MROW_F 24704                // [128]
#define LROW_F 24832                // [128]
#define MKT_F  24960                // [16][128]
#define SMEM_F 27008                // total floats (105.5 KB)

__global__ __launch_bounds__(256) void attn_kernel(
    float* __restrict__ attn_out, float* __restrict__ ctx_out)
{
    extern __shared__ float sm[];
    float* Qs   = sm + QS_F;
    float* Kts  = sm + KT_F;
    float* Pt   = sm + PT_F;
    float* Vs   = sm + VS_F;
    float* mrow = sm + MROW_F;
    float* lrow = sm + LROW_F;
    float* mkt  = sm + MKT_F;

    const int tid = threadIdx.x;
    const int tx = tid & 15;
    const int ty = tid >> 4;
    const int n  = blockIdx.y;
    const int r0 = blockIdx.x * 128;
    const float scale = 0.125f;  // 1/sqrt(64)

    const float* Qn = g_q + (size_t)n * SEQ * DHEAD;
    const float* Kn = g_k + (size_t)n * SEQ * DHEAD;
    const float* Vn = g_v + (size_t)n * SEQ * DHEAD;
    float* Sn = g_stage + (size_t)n * SEQ * SEQ;
    float* An = attn_out + (size_t)n * SEQ * SEQ;

    // Load Q tile transposed: Qs[d][i]
#pragma unroll
    for (int l = 0; l < 8; l++) {
        int id = tid + l * 256;      // 2048 float4 slots
        int i  = id >> 4;
        int dq = (id & 15) << 2;
        float4 v4 = *reinterpret_cast<const float4*>(&Qn[(size_t)(r0 + i) * DHEAD + dq]);
        Qs[(dq + 0) * 128 + i] = v4.x;
        Qs[(dq + 1) * 128 + i] = v4.y;
        Qs[(dq + 2) * 128 + i] = v4.z;
        Qs[(dq + 3) * 128 + i] = v4.w;
    }
    if (tid < 128) { mrow[tid] = -1e30f; lrow[tid] = 0.0f; }
    __syncthreads();

    // ------------------------- Phase 1 -------------------------
    for (int kt = 0; kt < SEQ / 128; kt++) {
#pragma unroll
        for (int l = 0; l < 8; l++) {
            int id = tid + l * 256;
            int j  = id >> 4;
            int dq = (id & 15) << 2;
            float4 v4 = *reinterpret_cast<const float4*>(
                &Kn[(size_t)(kt * 128 + j) * DHEAD + dq]);
            Kts[(dq + 0) * 128 + j] = v4.x;
            Kts[(dq + 1) * 128 + j] = v4.y;
            Kts[(dq + 2) * 128 + j] = v4.z;
            Kts[(dq + 3) * 128 + j] = v4.w;
        }
        __syncthreads();

        unsigned long long acc[8][4];
#pragma unroll
        for (int r = 0; r < 8; r++)
#pragma unroll
            for (int c = 0; c < 4; c++) acc[r][c] = 0ull;

#pragma unroll 8
        for (int kk = 0; kk < DHEAD; kk++) {
            const float* ar = &Qs[kk * 128];
            const float* br = &Kts[kk * 128];
            float4 af0 = *reinterpret_cast<const float4*>(ar + ty * 4);
            float4 af1 = *reinterpret_cast<const float4*>(ar + 64 + ty * 4);
            const unsigned long long* bp0 =
                reinterpret_cast<const unsigned long long*>(br + tx * 4);
            const unsigned long long* bp1 =
                reinterpret_cast<const unsigned long long*>(br + 64 + tx * 4);
            unsigned long long b0 = bp0[0], b1 = bp0[1], b2 = bp1[0], b3 = bp1[1];
            unsigned long long ap[8] = {pack2(af0.x), pack2(af0.y), pack2(af0.z), pack2(af0.w),
                                        pack2(af1.x), pack2(af1.y), pack2(af1.z), pack2(af1.w)};
#pragma unroll
            for (int r = 0; r < 8; r++) {
                acc[r][0] = fma2(ap[r], b0, acc[r][0]);
                acc[r][1] = fma2(ap[r], b1, acc[r][1]);
                acc[r][2] = fma2(ap[r], b2, acc[r][2]);
                acc[r][3] = fma2(ap[r], b3, acc[r][3]);
            }
        }

        // stats + write exp(s - m_tile) to stage
#pragma unroll
        for (int r = 0; r < 8; r++) {
            int row = ty * 4 + (r & 3) + ((r >> 2) << 6);
            float s8[8];
#pragma unroll
            for (int c = 0; c < 4; c++) {
                float2 v = unpack2(acc[r][c]);
                // c -> cols: tx*4 + (c&1)*2 + (c>>1)*64
                s8[((c >> 1) << 2) + ((c & 1) << 1) + 0] = v.x * scale;
                s8[((c >> 1) << 2) + ((c & 1) << 1) + 1] = v.y * scale;
            }
            float tm = s8[0];
#pragma unroll
            for (int c = 1; c < 8; c++) tm = fmaxf(tm, s8[c]);
#pragma unroll
            for (int m = 8; m >= 1; m >>= 1)
                tm = fmaxf(tm, __shfl_xor_sync(0xffffffffu, tm, m));
            float m_old = mrow[row];
            float m_new = fmaxf(m_old, tm);
            float e8[8];
            float ts = 0.0f;
#pragma unroll
            for (int c = 0; c < 8; c++) { e8[c] = __expf(s8[c] - m_new); ts += e8[c]; }
            float* sp = &Sn[(size_t)(r0 + row) * SEQ + kt * 128];
            *reinterpret_cast<float4*>(sp + tx * 4)      = make_float4(e8[0], e8[1], e8[2], e8[3]);
            *reinterpret_cast<float4*>(sp + 64 + tx * 4) = make_float4(e8[4], e8[5], e8[6], e8[7]);
#pragma unroll
            for (int m = 8; m >= 1; m >>= 1)
                ts += __shfl_xor_sync(0xffffffffu, ts, m);
            if (tx == 0) {
                lrow[row] = lrow[row] * __expf(m_old - m_new) + ts;
                mrow[row] = m_new;
                mkt[kt * 128 + row] = m_new;
            }
        }
        __syncthreads();
    }

    if (tid < 128) lrow[tid] = 1.0f / lrow[tid];
    __syncthreads();

    // ------------------------- Phase 2 -------------------------
    unsigned long long acc2[8][2];
#pragma unroll
    for (int r = 0; r < 8; r++) { acc2[r][0] = 0ull; acc2[r][1] = 0ull; }

    const int h  = n >> 1;
    const int b_ = n & 1;

    for (int kt = 0; kt < SEQ / 128; kt++) {
        // V tile [128][64]
#pragma unroll
        for (int l = 0; l < 8; l++) {
            int id = tid + l * 256;
            int j  = id >> 4;
            int dq = (id & 15) << 2;
            *reinterpret_cast<float4*>(&Vs[j * 64 + dq]) =
                *reinterpret_cast<const float4*>(&Vn[(size_t)(kt * 128 + j) * DHEAD + dq]);
        }
        // normalize + write attn + stage P transposed
#pragma unroll
        for (int l = 0; l < 16; l++) {
            int id  = tid + l * 256;     // 4096 float4 slots
            int row = id >> 5;
            int c4  = (id & 31) << 2;
            size_t off = (size_t)(r0 + row) * SEQ + kt * 128 + c4;
            float4 v = *reinterpret_cast<const float4*>(&Sn[off]);
            float cf = __expf(mkt[kt * 128 + row] - mrow[row]) * lrow[row];
            v.x *= cf; v.y *= cf; v.z *= cf; v.w *= cf;
            *reinterpret_cast<float4*>(&An[off]) = v;
            Pt[(c4 + 0) * 129 + row] = v.x;
            Pt[(c4 + 1) * 129 + row] = v.y;
            Pt[(c4 + 2) * 129 + row] = v.z;
            Pt[(c4 + 3) * 129 + row] = v.w;
        }
        __syncthreads();

#pragma unroll 4
        for (int kk = 0; kk < 128; kk++) {
            const float* pr = &Pt[kk * 129];
            const unsigned long long* bp =
                reinterpret_cast<const unsigned long long*>(&Vs[kk * 64 + tx * 4]);
            unsigned long long b0 = bp[0], b1 = bp[1];
            unsigned long long ap[8] = {
                pack2(pr[ty * 4 + 0]), pack2(pr[ty * 4 + 1]),
                pack2(pr[ty * 4 + 2]), pack2(pr[ty * 4 + 3]),
                pack2(pr[64 + ty * 4 + 0]), pack2(pr[64 + ty * 4 + 1]),
                pack2(pr[64 + ty * 4 + 2]), pack2(pr[64 + ty * 4 + 3])};
#pragma unroll
            for (int r = 0; r < 8; r++) {
                acc2[r][0] = fma2(ap[r], b0, acc2[r][0]);
                acc2[r][1] = fma2(ap[r], b1, acc2[r][1]);
            }
        }
        __syncthreads();
    }

    // ctx epilogue: out[b][s][h*64 + d]
#pragma unroll
    for (int r = 0; r < 8; r++) {
        int row = ty * 4 + (r & 3) + ((r >> 2) << 6);
        int s_  = r0 + row;
#pragma unroll
        for (int q = 0; q < 2; q++) {
            float2 v = unpack2(acc2[r][q]);
            int d = tx * 4 + q * 2;
            *reinterpret_cast<float2*>(
                &ctx_out[((size_t)b_ * SEQ + s_) * D_MODEL + h * 64 + d]) = v;
        }
    }
}

// ============================================================================
extern "C" void kernel_launch(void* const* d_in, const int* in_sizes, int n_in,
                              void* d_out, int out_size)
{
    const float* query = (const float*)d_in[0];
    const float* key_  = (const float*)d_in[1];
    const float* value = (const float*)d_in[2];
    const float* Wq = (const float*)d_in[3];
    const float* bq = (const float*)d_in[4];
    const float* Wk = (const float*)d_in[5];
    const float* bk = (const float*)d_in[6];
    const float* Wv = (const float*)d_in[7];
    const float* bv = (const float*)d_in[8];

    cudaFuncSetAttribute(attn_kernel, cudaFuncAttributeMaxDynamicSharedMemorySize,
                         SMEM_F * sizeof(float));

    // Resolve output layout: reference returns (context, attn).
    const long long CTX_N  = (long long)MROWS * D_MODEL;       // 4194304
    const long long ATTN_N = (long long)HB * SEQ * SEQ;        // 134217728
    float* ctx_out;
    float* attn_out;
    void* sym;
    if ((long long)out_size >= CTX_N + ATTN_N) {
        ctx_out  = (float*)d_out;
        attn_out = (float*)d_out + CTX_N;
    } else if ((long long)out_size == ATTN_N) {
        attn_out = (float*)d_out;
        cudaGetSymbolAddress(&sym, g_ctx_fb);
        ctx_out = (float*)sym;
    } else {
        ctx_out = (float*)d_out;
        cudaGetSymbolAddress(&sym, g_stage);   // normalize in place into stage
        attn_out = (float*)sym;
    }

    dim3 pgrid(D_MODEL / 128, MROWS / 128);   // (8, 32)
    proj_kernel<<<pgrid, 256>>>(query, Wq, bq, 0);
    proj_kernel<<<pgrid, 256>>>(key_,  Wk, bk, 1);
    proj_kernel<<<pgrid, 256>>>(value, Wv, bv, 2);

    dim3 agrid(SEQ / 128, HB);                // (16, 32)
    attn_kernel<<<agrid, 256, SMEM_F * sizeof(float)>>>(attn_out, ctx_out);
}

// round 3
// speedup vs baseline: 1.9589x; 1.9589x over previous
#include <cuda_runtime.h>
#include <cuda_bf16.h>

#define D_MODEL 1024
#define SEQ     2048
#define BATCH   2
#define NHEAD   16
#define DHEAD   64
#define HB      32
#define MROWS   4096

typedef unsigned int u32;
typedef unsigned short u16;

// ---- device-global scratch (allocation-free) ----
__device__ u16 g_qh[(size_t)HB * SEQ * DHEAD];
__device__ u16 g_ql[(size_t)HB * SEQ * DHEAD];
__device__ u16 g_kh[(size_t)HB * SEQ * DHEAD];
__device__ u16 g_kl[(size_t)HB * SEQ * DHEAD];
__device__ u16 g_vh[(size_t)HB * SEQ * DHEAD];
__device__ u16 g_vl[(size_t)HB * SEQ * DHEAD];
__device__ float g_attn_fb[(size_t)HB * SEQ * SEQ];   // fallback sinks
__device__ float g_ctx_fb[(size_t)MROWS * D_MODEL];

// ---- PTX primitives ----
__device__ __forceinline__ void ldm_x4(u32 r[4], u32 addr) {
    asm volatile("ldmatrix.sync.aligned.m8n8.x4.shared.b16 {%0,%1,%2,%3}, [%4];"
                 : "=r"(r[0]), "=r"(r[1]), "=r"(r[2]), "=r"(r[3]) : "r"(addr));
}
__device__ __forceinline__ void ldm_x2(u32 r[2], u32 addr) {
    asm volatile("ldmatrix.sync.aligned.m8n8.x2.shared.b16 {%0,%1}, [%2];"
                 : "=r"(r[0]), "=r"(r[1]) : "r"(addr));
}
__device__ __forceinline__ void ldm_x2t(u32 r[2], u32 addr) {
    asm volatile("ldmatrix.sync.aligned.m8n8.x2.trans.shared.b16 {%0,%1}, [%2];"
                 : "=r"(r[0]), "=r"(r[1]) : "r"(addr));
}
__device__ __forceinline__ void mma16816(float d[4], const u32 a[4], const u32 b[2]) {
    asm volatile("mma.sync.aligned.m16n8k16.row.col.f32.bf16.bf16.f32 "
                 "{%0,%1,%2,%3}, {%4,%5,%6,%7}, {%8,%9}, {%0,%1,%2,%3};"
                 : "+f"(d[0]), "+f"(d[1]), "+f"(d[2]), "+f"(d[3])
                 : "r"(a[0]), "r"(a[1]), "r"(a[2]), "r"(a[3]), "r"(b[0]), "r"(b[1]));
}
__device__ __forceinline__ u32 smem_u32(const void* p) {
    return (u32)__cvta_generic_to_shared(p);
}
// split (x,y) into bf16 hi pair (ret) + lo pair (out param)
__device__ __forceinline__ u32 pack_pair(float x, float y, u32& lo2) {
    __nv_bfloat162 h2 = __floats2bfloat162_rn(x, y);
    float2 hf = __bfloat1622float2(h2);
    __nv_bfloat162 l2 = __floats2bfloat162_rn(x - hf.x, y - hf.y);
    lo2 = *reinterpret_cast<u32*>(&l2);
    return *reinterpret_cast<u32*>(&h2);
}

// ============================================================================
// Projection: C = X @ W^T + b -> bf16 hi/lo, head-permuted [H*B, S, Dh].
// CTA 128x128, BK=32, 8 warps (4m x 2n), warp tile 32x64. bf16x3 MMA.
// ============================================================================
#define PJ_STR 40   // smem row stride (bf16 elems) for 32-wide k tiles

__global__ __launch_bounds__(256) void proj_kernel(
    const float* __restrict__ X, const float* __restrict__ W,
    const float* __restrict__ bias, int which)
{
    u16* outh = (which == 0) ? g_qh : (which == 1) ? g_kh : g_vh;
    u16* outl = (which == 0) ? g_ql : (which == 1) ? g_kl : g_vl;

    __shared__ u16 sAh[128 * PJ_STR], sAl[128 * PJ_STR];
    __shared__ u16 sBh[128 * PJ_STR], sBl[128 * PJ_STR];

    const int tid = threadIdx.x;
    const int lane = tid & 31;
    const int wid = tid >> 5;
    const int wm = wid >> 1, wn = wid & 1;
    const int m0c = blockIdx.y * 128;
    const int n0c = blockIdx.x * 128;

    const u32 aAh = smem_u32(sAh), aAl = smem_u32(sAl);
    const u32 aBh = smem_u32(sBh), aBl = smem_u32(sBl);

    float acc[2][8][4];
#pragma unroll
    for (int mf = 0; mf < 2; mf++)
#pragma unroll
        for (int nf = 0; nf < 8; nf++)
#pragma unroll
            for (int q = 0; q < 4; q++) acc[mf][nf][q] = 0.0f;

    for (int k0 = 0; k0 < D_MODEL; k0 += 32) {
#pragma unroll
        for (int i = 0; i < 4; i++) {
            int id  = tid + i * 256;        // 1024 float4 slots
            int row = id >> 3;
            int c4  = (id & 7) << 2;        // 0..28
            float4 v = *reinterpret_cast<const float4*>(
                &X[(size_t)(m0c + row) * D_MODEL + k0 + c4]);
            u32 la, ha = (la = 0, pack_pair(v.x, v.y, la));
            u32 lb, hb = (lb = 0, pack_pair(v.z, v.w, lb));
            *reinterpret_cast<u32*>(&sAh[row * PJ_STR + c4])     = ha;
            *reinterpret_cast<u32*>(&sAh[row * PJ_STR + c4 + 2]) = hb;
            *reinterpret_cast<u32*>(&sAl[row * PJ_STR + c4])     = la;
            *reinterpret_cast<u32*>(&sAl[row * PJ_STR + c4 + 2]) = lb;
            float4 w = *reinterpret_cast<const float4*>(
                &W[(size_t)(n0c + row) * D_MODEL + k0 + c4]);
            u32 lc, hc = (lc = 0, pack_pair(w.x, w.y, lc));
            u32 ld, hd = (ld = 0, pack_pair(w.z, w.w, ld));
            *reinterpret_cast<u32*>(&sBh[row * PJ_STR + c4])     = hc;
            *reinterpret_cast<u32*>(&sBh[row * PJ_STR + c4 + 2]) = hd;
            *reinterpret_cast<u32*>(&sBl[row * PJ_STR + c4])     = lc;
            *reinterpret_cast<u32*>(&sBl[row * PJ_STR + c4 + 2]) = ld;
        }
        __syncthreads();

#pragma unroll
        for (int ks = 0; ks < 32; ks += 16) {
            u32 ah[2][4], al[2][4];
#pragma unroll
            for (int mf = 0; mf < 2; mf++) {
                u32 off = ((wm * 32 + mf * 16 + (lane & 15)) * PJ_STR +
                           ks + ((lane >> 4) << 3)) * 2;
                ldm_x4(ah[mf], aAh + off);
                ldm_x4(al[mf], aAl + off);
            }
#pragma unroll
            for (int nf = 0; nf < 8; nf++) {
                int l16 = lane & 15;
                u32 off = ((wn * 64 + nf * 8 + (l16 & 7)) * PJ_STR +
                           ks + ((l16 >> 3) << 3)) * 2;
                u32 bh[2], bl[2];
                ldm_x2(bh, aBh + off);
                ldm_x2(bl, aBl + off);
#pragma unroll
                for (int mf = 0; mf < 2; mf++) {
                    mma16816(acc[mf][nf], ah[mf], bh);
                    mma16816(acc[mf][nf], ah[mf], bl);
                    mma16816(acc[mf][nf], al[mf], bh);
                }
            }
        }
        __syncthreads();
    }

    // epilogue: bias + split + permuted store
#pragma unroll
    for (int mf = 0; mf < 2; mf++) {
#pragma unroll
        for (int nf = 0; nf < 8; nf++) {
            int col = n0c + wn * 64 + nf * 8 + ((lane & 3) << 1);
            float b0 = bias[col], b1 = bias[col + 1];
            int h = col >> 6, d = col & 63;
#pragma unroll
            for (int half = 0; half < 2; half++) {
                int gi = m0c + wm * 32 + mf * 16 + (lane >> 2) + half * 8;
                int b_ = gi >> 11, s_ = gi & (SEQ - 1);
                float x = acc[mf][nf][half * 2]     + b0;
                float y = acc[mf][nf][half * 2 + 1] + b1;
                u32 lo2, hi2 = pack_pair(x, y, lo2);
                size_t idx = ((size_t)(h * BATCH + b_) * SEQ + s_) * DHEAD + d;
                *reinterpret_cast<u32*>(&outh[idx]) = hi2;
                *reinterpret_cast<u32*>(&outl[idx]) = lo2;
            }
        }
    }
}

// ============================================================================
// Attention: CTA = (n, 128 q-rows). Phase 1: stats only (no S writes).
// Phase 2: recompute S, normalize -> attn gmem + P smem -> PV MMA.
// ============================================================================
// smem byte offsets
#define O_QH 0
#define O_QL 18432
#define O_KH 36864
#define O_KL 55296
#define O_VH 73728
#define O_VL 92160
#define O_PH 110592
#define O_PL 145408
#define O_MR 180224
#define O_LR 180736
#define O_PM 181248
#define O_PL2 182272
#define ATTN_SMEM 183296

__device__ __forceinline__ void load_tile64(u16* dst, const u16* src, int tid) {
#pragma unroll
    for (int i = 0; i < 4; i++) {
        int id = tid + i * 256;
        int row = id >> 3, c = id & 7;
        *reinterpret_cast<uint4*>(dst + row * 72 + c * 8) =
            *reinterpret_cast<const uint4*>(src + (size_t)row * 64 + c * 8);
    }
}

__device__ __forceinline__ void qk_mma(u32 aQH, u32 aQL, u32 aKH, u32 aKL,
                                       int m0w, int n0w, int lane,
                                       float sacc[2][8][4]) {
#pragma unroll
    for (int ks = 0; ks < 64; ks += 16) {
        u32 ah[2][4], al[2][4];
#pragma unroll
        for (int mf = 0; mf < 2; mf++) {
            u32 off = ((m0w + mf * 16 + (lane & 15)) * 72 +
                       ks + ((lane >> 4) << 3)) * 2;
            ldm_x4(ah[mf], aQH + off);
            ldm_x4(al[mf], aQL + off);
        }
#pragma unroll
        for (int nf = 0; nf < 8; nf++) {
            int l16 = lane & 15;
            u32 off = ((n0w + nf * 8 + (l16 & 7)) * 72 +
                       ks + ((l16 >> 3) << 3)) * 2;
            u32 bh[2], bl[2];
            ldm_x2(bh, aKH + off);
            ldm_x2(bl, aKL + off);
#pragma unroll
            for (int mf = 0; mf < 2; mf++) {
                mma16816(sacc[mf][nf], ah[mf], bh);
                mma16816(sacc[mf][nf], ah[mf], bl);
                mma16816(sacc[mf][nf], al[mf], bh);
            }
        }
    }
}

__global__ __launch_bounds__(256) void attn_kernel(
    float* __restrict__ attn_out, float* __restrict__ ctx_out)
{
    extern __shared__ char sm[];
    u16* sQH = (u16*)(sm + O_QH);  u16* sQL = (u16*)(sm + O_QL);
    u16* sKH = (u16*)(sm + O_KH);  u16* sKL = (u16*)(sm + O_KL);
    u16* sVH = (u16*)(sm + O_VH);  u16* sVL = (u16*)(sm + O_VL);
    u16* sPH = (u16*)(sm + O_PH);  u16* sPL = (u16*)(sm + O_PL);
    float* mrow = (float*)(sm + O_MR);
    float* lrow = (float*)(sm + O_LR);
    float* pm   = (float*)(sm + O_PM);
    float* pl   = (float*)(sm + O_PL2);

    const u32 aQH = smem_u32(sQH), aQL = smem_u32(sQL);
    const u32 aKH = smem_u32(sKH), aKL = smem_u32(sKL);
    const u32 aVH = smem_u32(sVH), aVL = smem_u32(sVL);
    const u32 aPH = smem_u32(sPH), aPL = smem_u32(sPL);

    const int tid = threadIdx.x;
    const int lane = tid & 31;
    const int wid = tid >> 5;
    const int wm = wid >> 1, wn = wid & 1;
    const int m0w = wm * 32, n0w = wn * 64;
    const int n  = blockIdx.y;
    const int r0 = blockIdx.x * 128;
    const float scale = 0.125f;

    const size_t nbase = (size_t)n * SEQ * DHEAD;
    float* An = attn_out + (size_t)n * SEQ * SEQ;

    load_tile64(sQH, g_qh + nbase + (size_t)r0 * DHEAD, tid);
    load_tile64(sQL, g_ql + nbase + (size_t)r0 * DHEAD, tid);
    if (tid < 128) { mrow[tid] = -1e30f; lrow[tid] = 0.0f; }

    // ---------------- Phase 1: stats ----------------
    for (int kt = 0; kt < SEQ / 128; kt++) {
        load_tile64(sKH, g_kh + nbase + (size_t)kt * 128 * DHEAD, tid);
        load_tile64(sKL, g_kl + nbase + (size_t)kt * 128 * DHEAD, tid);
        __syncthreads();

        float sacc[2][8][4];
#pragma unroll
        for (int mf = 0; mf < 2; mf++)
#pragma unroll
            for (int nf = 0; nf < 8; nf++)
#pragma unroll
                for (int q = 0; q < 4; q++) sacc[mf][nf][q] = 0.0f;
        qk_mma(aQH, aQL, aKH, aKL, m0w, n0w, lane, sacc);

#pragma unroll
        for (int mf = 0; mf < 2; mf++) {
#pragma unroll
            for (int half = 0; half < 2; half++) {
                int rl = m0w + mf * 16 + (lane >> 2) + half * 8;
                float mx = -1e30f;
#pragma unroll
                for (int nf = 0; nf < 8; nf++) {
                    mx = fmaxf(mx, fmaxf(sacc[mf][nf][half * 2] * scale,
                                         sacc[mf][nf][half * 2 + 1] * scale));
                }
                mx = fmaxf(mx, __shfl_xor_sync(0xffffffffu, mx, 1));
                mx = fmaxf(mx, __shfl_xor_sync(0xffffffffu, mx, 2));
                float sum = 0.0f;
#pragma unroll
                for (int nf = 0; nf < 8; nf++) {
                    sum += __expf(sacc[mf][nf][half * 2] * scale - mx);
                    sum += __expf(sacc[mf][nf][half * 2 + 1] * scale - mx);
                }
                sum += __shfl_xor_sync(0xffffffffu, sum, 1);
                sum += __shfl_xor_sync(0xffffffffu, sum, 2);
                if ((lane & 3) == 0) { pm[rl * 2 + wn] = mx; pl[rl * 2 + wn] = sum; }
            }
        }
        __syncthreads();
        if (tid < 128) {
            float m0 = pm[tid * 2], m1 = pm[tid * 2 + 1];
            float mt = fmaxf(m0, m1);
            float lt = pl[tid * 2] * __expf(m0 - mt) + pl[tid * 2 + 1] * __expf(m1 - mt);
            float mo = mrow[tid];
            float mn = fmaxf(mo, mt);
            lrow[tid] = lrow[tid] * __expf(mo - mn) + lt * __expf(mt - mn);
            mrow[tid] = mn;
        }
        __syncthreads();
    }

    if (tid < 128) lrow[tid] = 1.0f / lrow[tid];

    // ---------------- Phase 2: recompute + normalize + PV ----------------
    float cacc[2][4][4];
#pragma unroll
    for (int mf = 0; mf < 2; mf++)
#pragma unroll
        for (int nf = 0; nf < 4; nf++)
#pragma unroll
            for (int q = 0; q < 4; q++) cacc[mf][nf][q] = 0.0f;

    for (int kt = 0; kt < SEQ / 128; kt++) {
        load_tile64(sKH, g_kh + nbase + (size_t)kt * 128 * DHEAD, tid);
        load_tile64(sKL, g_kl + nbase + (size_t)kt * 128 * DHEAD, tid);
        load_tile64(sVH, g_vh + nbase + (size_t)kt * 128 * DHEAD, tid);
        load_tile64(sVL, g_vl + nbase + (size_t)kt * 128 * DHEAD, tid);
        __syncthreads();

        float sacc[2][8][4];
#pragma unroll
        for (int mf = 0; mf < 2; mf++)
#pragma unroll
            for (int nf = 0; nf < 8; nf++)
#pragma unroll
                for (int q = 0; q < 4; q++) sacc[mf][nf][q] = 0.0f;
        qk_mma(aQH, aQL, aKH, aKL, m0w, n0w, lane, sacc);

#pragma unroll
        for (int mf = 0; mf < 2; mf++) {
#pragma unroll
            for (int half = 0; half < 2; half++) {
                int rl = m0w + mf * 16 + (lane >> 2) + half * 8;
                float mr = mrow[rl], li = lrow[rl];
                float* anrow = An + (size_t)(r0 + rl) * SEQ + kt * 128;
#pragma unroll
                for (int nf = 0; nf < 8; nf++) {
                    float p0 = __expf(sacc[mf][nf][half * 2] * scale - mr) * li;
                    float p1 = __expf(sacc[mf][nf][half * 2 + 1] * scale - mr) * li;
                    int col = n0w + nf * 8 + ((lane & 3) << 1);
                    *reinterpret_cast<float2*>(anrow + col) = make_float2(p0, p1);
                    u32 lo2, hi2 = pack_pair(p0, p1, lo2);
                    *reinterpret_cast<u32*>(&sPH[rl * 136 + col]) = hi2;
                    *reinterpret_cast<u32*>(&sPL[rl * 136 + col]) = lo2;
                }
            }
        }
        __syncthreads();

        // PV: ctx += P[128x128] @ V[128x64]; warp tile 32x32
#pragma unroll
        for (int ks = 0; ks < 8; ks++) {
            int k0 = ks * 16;
            u32 ah[2][4], al[2][4];
#pragma unroll
            for (int mf = 0; mf < 2; mf++) {
                u32 off = ((m0w + mf * 16 + (lane & 15)) * 136 +
                           k0 + ((lane >> 4) << 3)) * 2;
                ldm_x4(ah[mf], aPH + off);
                ldm_x4(al[mf], aPL + off);
            }
#pragma unroll
            for (int nf = 0; nf < 4; nf++) {
                int d0 = wn * 32 + nf * 8;
                u32 off = ((k0 + (lane & 15)) * 72 + d0) * 2;
                u32 bh[2], bl[2];
                ldm_x2t(bh, aVH + off);
                ldm_x2t(bl, aVL + off);
#pragma unroll
                for (int mf = 0; mf < 2; mf++) {
                    mma16816(cacc[mf][nf], ah[mf], bh);
                    mma16816(cacc[mf][nf], ah[mf], bl);
                    mma16816(cacc[mf][nf], al[mf], bh);
                }
            }
        }
        __syncthreads();
    }

    // ctx epilogue: out[b][s][h*64+d]
    const int h = n >> 1, b_ = n & 1;
#pragma unroll
    for (int mf = 0; mf < 2; mf++) {
#pragma unroll
        for (int nf = 0; nf < 4; nf++) {
            int d = wn * 32 + nf * 8 + ((lane & 3) << 1);
#pragma unroll
            for (int half = 0; half < 2; half++) {
                int s_ = r0 + m0w + mf * 16 + (lane >> 2) + half * 8;
                float2 v = make_float2(cacc[mf][nf][half * 2],
                                       cacc[mf][nf][half * 2 + 1]);
                *reinterpret_cast<float2*>(
                    &ctx_out[((size_t)b_ * SEQ + s_) * D_MODEL + h * 64 + d]) = v;
            }
        }
    }
}

// ============================================================================
extern "C" void kernel_launch(void* const* d_in, const int* in_sizes, int n_in,
                              void* d_out, int out_size)
{
    const float* query = (const float*)d_in[0];
    const float* key_  = (const float*)d_in[1];
    const float* value = (const float*)d_in[2];
    const float* Wq = (const float*)d_in[3];
    const float* bq = (const float*)d_in[4];
    const float* Wk = (const float*)d_in[5];
    const float* bk = (const float*)d_in[6];
    const float* Wv = (const float*)d_in[7];
    const float* bv = (const float*)d_in[8];

    cudaFuncSetAttribute(attn_kernel, cudaFuncAttributeMaxDynamicSharedMemorySize,
                         ATTN_SMEM);

    const long long CTX_N  = (long long)MROWS * D_MODEL;   // 4194304
    const long long ATTN_N = (long long)HB * SEQ * SEQ;    // 134217728
    float* ctx_out;
    float* attn_out;
    void* sym;
    if ((long long)out_size >= CTX_N + ATTN_N) {
        ctx_out  = (float*)d_out;
        attn_out = (float*)d_out + CTX_N;
    } else if ((long long)out_size == ATTN_N) {
        attn_out = (float*)d_out;
        cudaGetSymbolAddress(&sym, g_ctx_fb);
        ctx_out = (float*)sym;
    } else {
        ctx_out = (float*)d_out;
        cudaGetSymbolAddress(&sym, g_attn_fb);
        attn_out = (float*)sym;
    }

    dim3 pgrid(D_MODEL / 128, MROWS / 128);   // (8, 32)
    proj_kernel<<<pgrid, 256>>>(query, Wq, bq, 0);
    proj_kernel<<<pgrid, 256>>>(key_,  Wk, bk, 1);
    proj_kernel<<<pgrid, 256>>>(value, Wv, bv, 2);

    dim3 agrid(SEQ / 128, HB);                // (16, 32)
    attn_kernel<<<agrid, 256, ATTN_SMEM>>>(attn_out, ctx_out);
}